// round 13
// baseline (speedup 1.0000x reference)
#include <cuda_runtime.h>
#include <math.h>

#define NEXP 16
#define MAX_T 4096
#define NSPLIT 4

// Scratch (allocation-free per harness rules)
__device__ float g_part[NSPLIT * MAX_T * NEXP]; // per-(token,quarter) partials
__device__ float g_probs[NEXP * MAX_T];    // [e][t] for coalesced aux reduce
__device__ float g_s0[MAX_T];
__device__ float g_s1[MAX_T];
__device__ int   g_i0[MAX_T];
__device__ int   g_i1[MAX_T];

// ---------------------------------------------------------------------------
// Kernel 1a: partial gating. One warp per (token, H-quarter): 16 dots over
// H/4. 8192 warps in 1024 blocks -> deep latency hiding; per-warp chain is
// only 4 iterations of 17 independent LDG.128. Partials stored (no atomics)
// -> deterministic.
// ---------------------------------------------------------------------------
__global__ void gate_partial(const float4* __restrict__ hs,
                             const float4* __restrict__ gw,
                             int T, int H4) {
    int task = (blockIdx.x * blockDim.x + threadIdx.x) >> 5;
    int lane = threadIdx.x & 31;
    int t    = task >> 2;
    int part = task & 3;
    if (t >= T) return;

    const int H4q = H4 >> 2;
    const int h0  = part * H4q;
    const float4* hrow = hs + (size_t)t * H4 + h0;

    float acc[NEXP];
#pragma unroll
    for (int e = 0; e < NEXP; e++) acc[e] = 0.f;

    for (int h = lane; h < H4q; h += 32) {
        float4 hv = hrow[h];
#pragma unroll
        for (int e = 0; e < NEXP; e++) {
            float4 w = __ldg(&gw[(size_t)e * H4 + h0 + h]);
            acc[e] += fmaf(hv.x, w.x, hv.y * w.y)
                    + fmaf(hv.z, w.z, hv.w * w.w);
        }
    }

#pragma unroll
    for (int e = 0; e < NEXP; e++) {
#pragma unroll
        for (int off = 16; off; off >>= 1)
            acc[e] += __shfl_xor_sync(0xffffffffu, acc[e], off);
    }

    if (lane == 0) {
        float* dst = g_part + (size_t)task * NEXP;
#pragma unroll
        for (int e = 0; e < NEXP; e++) dst[e] = acc[e];
    }
}

// ---------------------------------------------------------------------------
// Kernel 1b: finish gating. One thread per token: sum NSPLIT partials (fixed
// order -> deterministic), softmax, top-2, renormalize.
// ---------------------------------------------------------------------------
__global__ void gate_finish(int T) {
    int t = blockIdx.x * blockDim.x + threadIdx.x;
    if (t >= T) return;

    float l[NEXP];
#pragma unroll
    for (int e = 0; e < NEXP; e++) l[e] = 0.f;
#pragma unroll
    for (int q = 0; q < NSPLIT; q++) {
        const float* pq = g_part + (size_t)(t * NSPLIT + q) * NEXP;
#pragma unroll
        for (int e = 0; e < NEXP; e++) l[e] += pq[e];
    }

    float m = l[0];
#pragma unroll
    for (int e = 1; e < NEXP; e++) m = fmaxf(m, l[e]);
    float p[NEXP];
    float sum = 0.f;
#pragma unroll
    for (int e = 0; e < NEXP; e++) { p[e] = __expf(l[e] - m); sum += p[e]; }
    float inv = 1.f / sum;
#pragma unroll
    for (int e = 0; e < NEXP; e++) {
        p[e] *= inv;
        g_probs[e * MAX_T + t] = p[e];
    }
    // top-2 (lowest index wins ties, matching lax.top_k)
    float b0 = -1.f, b1 = -1.f;
    int   bi0 = 0,   bi1 = 0;
#pragma unroll
    for (int e = 0; e < NEXP; e++) {
        if (p[e] > b0)      { b1 = b0; bi1 = bi0; b0 = p[e]; bi0 = e; }
        else if (p[e] > b1) { b1 = p[e]; bi1 = e; }
    }
    float s = 1.f / (b0 + b1);
    g_s0[t] = b0 * s;
    g_s1[t] = b1 * s;
    g_i0[t] = bi0;
    g_i1[t] = bi1;
}

// ---------------------------------------------------------------------------
// Kernel 2: bias = s0*eb[i0] + s1*eb[i1]. Proven kernel at the ~4.85TB/s
// DRAM-write ceiling (54us). 2 independent float4s/thread, __stcs streaming
// stores, eb L2-resident via __ldg. Aux fused into block (0,0).
// ---------------------------------------------------------------------------
__global__ void bias_kernel(const float* __restrict__ eb,
                            float* __restrict__ out,
                            int T, int V, int has_aux) {
    if (has_aux && blockIdx.x == 0 && blockIdx.y == 0) {
        __shared__ float su[NEXP];
        int w = threadIdx.x >> 5, lane = threadIdx.x & 31;   // 8 warps
#pragma unroll
        for (int half = 0; half < 2; half++) {
            int e = w + half * 8;
            float s = 0.f;
            for (int t = lane; t < T; t += 32)
                s += g_probs[e * MAX_T + t];
#pragma unroll
            for (int off = 16; off; off >>= 1)
                s += __shfl_xor_sync(0xffffffffu, s, off);
            if (lane == 0) su[e] = s / (float)T;
        }
        __syncthreads();
        if (threadIdx.x == 0) {
            float a = 0.f;
#pragma unroll
            for (int i = 0; i < NEXP; i++)
                a += su[i] * logf(su[i]);
            out[(size_t)T * V] = a * (float)NEXP;
        }
    }

    const int t = blockIdx.y;
    const int V4 = V >> 2;
    const float s0 = g_s0[t];
    const float s1 = g_s1[t];
    const float4* e0 = (const float4*)(eb + (size_t)g_i0[t] * V);
    const float4* e1 = (const float4*)(eb + (size_t)g_i1[t] * V);
    float4* o = (float4*)(out + (size_t)t * V);

    int base = (blockIdx.x * blockDim.x) * 2 + threadIdx.x;
    int vA = base;
    int vB = base + blockDim.x;

    if (vA < V4) {
        float4 a0 = __ldg(&e0[vA]);
        float4 b0 = __ldg(&e1[vA]);
        bool hasB = (vB < V4);
        float4 a1, b1;
        if (hasB) { a1 = __ldg(&e0[vB]); b1 = __ldg(&e1[vB]); }

        float4 r0;
        r0.x = fmaf(s0, a0.x, s1 * b0.x);
        r0.y = fmaf(s0, a0.y, s1 * b0.y);
        r0.z = fmaf(s0, a0.z, s1 * b0.z);
        r0.w = fmaf(s0, a0.w, s1 * b0.w);
        __stcs(&o[vA], r0);

        if (hasB) {
            float4 r1;
            r1.x = fmaf(s0, a1.x, s1 * b1.x);
            r1.y = fmaf(s0, a1.y, s1 * b1.y);
            r1.z = fmaf(s0, a1.z, s1 * b1.z);
            r1.w = fmaf(s0, a1.w, s1 * b1.w);
            __stcs(&o[vB], r1);
        }
    }
}

extern "C" void kernel_launch(void* const* d_in, const int* in_sizes, int n_in,
                              void* d_out, int out_size) {
    const float* hs = (const float*)d_in[0];  // (T, H)
    const float* gw = (const float*)d_in[1];  // (E, H)
    const float* eb = (const float*)d_in[2];  // (E, V)
    float* out = (float*)d_out;

    int H = in_sizes[1] / NEXP;
    int T = in_sizes[0] / H;
    int V = in_sizes[2] / NEXP;
    int H4 = H >> 2;

    // 1a. partial gating: one warp per (token, quarter) -> 4T warps
    {
        int nwarps = T * NSPLIT;
        int threads = 256;
        int blocks = (nwarps * 32 + threads - 1) / threads;   // 1024
        gate_partial<<<blocks, threads>>>((const float4*)hs, (const float4*)gw,
                                          T, H4);
    }

    // 1b. finish gating: one thread per token
    gate_finish<<<(T + 255) / 256, 256>>>(T);

    // 2. bias (+fused aux): grid.x covers V4 with 2 float4/thread
    {
        long long tv = (long long)T * (long long)V;
        int has_aux = ((long long)out_size > tv) ? 1 : 0;
        int V4 = V >> 2;
        int threads = 256;
        int bx = (V4 + threads * 2 - 1) / (threads * 2);
        dim3 grid(bx, T);
        bias_kernel<<<grid, threads>>>(eb, out, T, V, has_aux);
    }
}